// round 3
// baseline (speedup 1.0000x reference)
#include <cuda_runtime.h>
#include <math.h>

#define En 512
#define Hn 1024
#define Cn 2048
#define Sn 256
#define Tn 128

#define OFF_PRE   (Tn*En)                 /* 65536  */
#define OFF_ALPHA (OFF_PRE + Tn*Hn)       /* 196608 */
#define OFF_H1F   (OFF_ALPHA + Tn*Sn)     /* 229376 */
#define OFF_H2F   (OFF_H1F + Hn)          /* 230400 */

#define NT 1024                            /* threads per block */

// ---------------- device scratch (static, no allocation) ----------------
__device__ float g_h1[Hn], g_h2[Hn], g_o1[Hn], g_o2[Hn];
__device__ float g_q[Hn], g_e[Sn], g_ctx[Cn];
__device__ float g_gh1[3*Hn], g_gh2[3*Hn];
__device__ float g_preacc[Hn];
__device__ float g_G1[Tn*3*Hn];      // precomputed W_ih1[:, :512] @ emb_t
__device__ float g_Gpre[Tn*Hn];      // precomputed W_pre[:, :512] @ emb_t
__device__ float g_encT[Cn*Sn];      // encoder_outputs transposed
__device__ unsigned g_flags[2048];   // per-block barrier flags, 32B stride

__global__ void init_kernel(const float* __restrict__ h1, const float* __restrict__ h2) {
    int i = blockIdx.x*blockDim.x + threadIdx.x;
    if (i < 2048) g_flags[i] = 0u;
    if (i < Hn) { g_h1[i] = h1[i]; g_h2[i] = h2[i]; }
}

__device__ __forceinline__ float warpsum(float s) {
#pragma unroll
    for (int o = 16; o; o >>= 1) s += __shfl_xor_sync(0xffffffffu, s, o);
    return s;
}

// warp-cooperative dot of one weight row (global) with a vector in shared mem
__device__ __forceinline__ float rowdot(const float* __restrict__ Wrow,
                                        const float* __restrict__ xs,
                                        int n4, int lane) {
    const float4* __restrict__ W4 = (const float4*)Wrow;
    const float4* __restrict__ X4 = (const float4*)xs;
    float s = 0.f;
#pragma unroll 8
    for (int k = lane; k < n4; k += 32) {
        float4 w = __ldg(W4 + k);
        float4 x = X4[k];
        s += w.x*x.x + w.y*x.y + w.z*x.z + w.w*x.w;
    }
    return warpsum(s);
}

// grid barrier: per-block flag store + warp-0 all-poll (no atomic serialization)
__device__ __forceinline__ void gsync(unsigned &ep, int bid, int nb) {
    ep++;
    __syncthreads();
    if (threadIdx.x == 0) {
        __threadfence();                              // release (CCTL.IVALL)
        ((volatile unsigned*)g_flags)[bid*8] = ep;    // parallel arrive
    }
    if (threadIdx.x < 32) {
        unsigned bad;
        do {
            bad = 0u;
#pragma unroll 1
            for (int b = threadIdx.x; b < nb; b += 32)
                bad |= (((volatile unsigned*)g_flags)[b*8] < ep) ? 1u : 0u;
        } while (__any_sync(0xffffffffu, bad));
        if (threadIdx.x == 0) __threadfence();        // acquire (invalidate L1D)
    }
    __syncthreads();
}

extern "C" __global__ void __launch_bounds__(NT, 1)
decoder_persistent(
    const int*   __restrict__ inputs,
    const float* __restrict__ pk,
    const float* __restrict__ enc,
    const float* __restrict__ embeds,
    const float* __restrict__ Wq,
    const float* __restrict__ v_att,
    const float* __restrict__ W_ih1,
    const float* __restrict__ W_hh1,
    const float* __restrict__ b_ih1,
    const float* __restrict__ b_hh1,
    const float* __restrict__ W_ih2,
    const float* __restrict__ W_hh2,
    const float* __restrict__ b_ih2,
    const float* __restrict__ b_hh2,
    const float* __restrict__ W_pre,
    const float* __restrict__ b_pre,
    const float* __restrict__ W_out,
    const float* __restrict__ b_out,
    float* __restrict__ out)
{
    __shared__ __align__(16) float s_x[8192];     // 32 KB staging
    __shared__ __align__(16) float s_alpha[Sn];
    __shared__ float s_pair[16*4];                // warp-pair partials (phase A)
    __shared__ float s_gi[48];
    __shared__ float s_inv;

    const int tid  = threadIdx.x;
    const int lane = tid & 31;
    const int wid  = tid >> 5;                    // 0..31
    const int nb   = gridDim.x;
    const int bid  = blockIdx.x;
    const int nwg  = nb * 32;                     // total warps in grid
    const int gw   = bid*32 + wid;                // global warp id
    unsigned ep = 0;

    // ======================= PROLOGUE =======================
    // 1) transpose encoder_outputs -> encT[c][s]
    for (int idx = bid*NT + tid; idx < Cn*Sn; idx += nb*NT) {
        int c = idx >> 8, s = idx & 255;
        g_encT[idx] = enc[(size_t)s*Cn + c];
    }
    // 2) emb-part GEMMs: rows 0..3071 = W_ih1[:, :512], rows 3072..4095 = W_pre[:, :512]
    {
        const int RT = 4*Hn;                       // 4096 rows
        int rb = (RT + nb - 1)/nb;
        int r0 = bid*rb, r1 = min(RT, r0 + rb);
        for (int tile = 0; tile < Tn/16; tile++) {
            __syncthreads();
            for (int idx = tid; idx < 16*En; idx += NT) {
                int tt = idx >> 9, c = idx & 511;
                s_x[idx] = embeds[(size_t)inputs[tile*16 + tt]*En + c];
            }
            __syncthreads();
            for (int rI = r0 + wid; rI < r1; rI += 32) {
                const float* Wrow; float* Gp; int gs;
                if (rI < 3*Hn) { Wrow = W_ih1 + (size_t)rI*2560;          Gp = g_G1  + rI;          gs = 3*Hn; }
                else           { Wrow = W_pre + (size_t)(rI - 3*Hn)*3584; Gp = g_Gpre + (rI - 3*Hn); gs = Hn;  }
                float w[16];
#pragma unroll
                for (int k = 0; k < 16; k++) w[k] = __ldg(Wrow + k*32 + lane);
#pragma unroll
                for (int tt = 0; tt < 16; tt++) {
                    float s = 0.f;
#pragma unroll
                    for (int k = 0; k < 16; k++) s += w[k] * s_x[tt*512 + k*32 + lane];
                    s = warpsum(s);
                    if (lane == 0) Gp[(tile*16 + tt)*gs] = s;
                }
            }
        }
    }
    gsync(ep, bid, nb);

    const int GPB = (Hn + nb - 1)/nb;               // GRU rows owned per block
    const int i0  = bid*GPB;
    const int ng  = max(0, min(GPB, Hn - i0));

    // ======================= MAIN SEQUENTIAL LOOP =======================
    for (int t = 0; t < Tn; t++) {
        // ---- Phase A: q=Wq@h2, gh1=Whh1@h1+b, gh2=Whh2@h2+b, (t>0) out[t-1], pre[t-1]
        //      warp-pair half-row GEMV: 8704 rows, pair gp handles rows [c0,c1)
        for (int i = tid; i < Hn; i += NT) {
            s_x[i]        = g_h2[i];
            s_x[Hn + i]   = g_h1[i];
            s_x[2*Hn + i] = g_o2[i];
        }
        __syncthreads();
        {
            const int gp   = bid*16 + (wid >> 1);    // global pair id (0..nb*16-1)
            const int half = wid & 1;
            const int pl   = wid >> 1;               // pair-local id (0..15)
            const int npair = nb*16;
            const int c0 = (int)(((long long)gp     * 8704) / npair);
            const int c1 = (int)(((long long)(gp+1) * 8704) / npair);
            float p[4];
            const int nr = c1 - c0;                  // 3 or 4
            for (int j = 0; j < nr; j++) {
                int r = c0 + j;
                p[j] = 0.f;
                if (t == 0 && r >= 7168) continue;
                const float* Wrow; const float* xb;
                if      (r < 1024) { Wrow = Wq    + (size_t)r*Hn;           xb = s_x;        }
                else if (r < 4096) { Wrow = W_hh1 + (size_t)(r-1024)*Hn;    xb = s_x + Hn;   }
                else if (r < 7168) { Wrow = W_hh2 + (size_t)(r-4096)*Hn;    xb = s_x;        }
                else if (r < 7680) { Wrow = W_out + (size_t)(r-7168)*Hn;    xb = s_x + 2*Hn; }
                else               { Wrow = W_pre + (size_t)(r-7680)*3584 + 512; xb = s_x + 2*Hn; }
                const float4* W4 = (const float4*)Wrow + half*128;
                const float4* X4 = (const float4*)xb   + half*128;
                float s = 0.f;
#pragma unroll
                for (int k = 0; k < 4; k++) {
                    float4 w = __ldg(W4 + k*32 + lane);
                    float4 x = X4[k*32 + lane];
                    s += w.x*x.x + w.y*x.y + w.z*x.z + w.w*x.w;
                }
                p[j] = warpsum(s);
            }
            if (half && lane == 0)
                for (int j = 0; j < nr; j++) s_pair[pl*4 + j] = p[j];
            __syncthreads();
            if (!half && lane == 0) {
                for (int j = 0; j < nr; j++) {
                    int r = c0 + j;
                    if (t == 0 && r >= 7168) continue;
                    float tot = p[j] + s_pair[pl*4 + j];
                    if      (r < 1024) g_q[r] = tot;
                    else if (r < 4096) { int rr = r-1024; g_gh1[rr] = tot + b_hh1[rr]; }
                    else if (r < 7168) { int rr = r-4096; g_gh2[rr] = tot + b_hh2[rr]; }
                    else if (r < 7680) { int rr = r-7168; out[(size_t)(t-1)*En + rr] = tot + b_out[rr]; }
                    else {
                        int rr = r-7680;
                        float v = tot + g_preacc[rr] + b_pre[rr];
                        out[OFF_PRE + (size_t)(t-1)*Hn + rr] = (v >= 0.f) ? v : 0.01f*v;
                    }
                }
            }
        }
        gsync(ep, bid, nb);

        // ---- Phase B: attention energies e[s] = tanh(pk[s]+q) . v_att ----
        for (int i = tid; i < Hn; i += NT) s_x[i] = g_q[i];
        __syncthreads();
        if (gw < Sn) {
            const int r = gw;
            const float4* p4 = (const float4*)(pk + (size_t)r*Hn);
            const float4* x4 = (const float4*)s_x;
            const float4* v4 = (const float4*)v_att;
            float acc = 0.f;
#pragma unroll 4
            for (int k = lane; k < 256; k += 32) {
                float4 p = __ldg(p4 + k); float4 q = x4[k]; float4 v = __ldg(v4 + k);
                acc += tanhf(p.x + q.x)*v.x + tanhf(p.y + q.y)*v.y
                     + tanhf(p.z + q.z)*v.z + tanhf(p.w + q.w)*v.w;
            }
            acc = warpsum(acc);
            if (!lane) g_e[r] = acc;
        }
        gsync(ep, bid, nb);

        // ---- Phase C: per-block softmax (redundant, cheap) + context = alpha @ enc ----
        if (wid == 0) {
            float ev[8], m = -1e30f;
#pragma unroll
            for (int k = 0; k < 8; k++) { ev[k] = g_e[k*32 + lane]; m = fmaxf(m, ev[k]); }
#pragma unroll
            for (int o = 16; o; o >>= 1) m = fmaxf(m, __shfl_xor_sync(0xffffffffu, m, o));
            float sum = 0.f;
#pragma unroll
            for (int k = 0; k < 8; k++) { float a = expf(ev[k] - m); s_alpha[k*32 + lane] = a; sum += a; }
            sum = warpsum(sum);
            if (!lane) s_inv = 1.f/sum;
        }
        __syncthreads();
        {
            float inv = s_inv;
            if (gw < Cn) {
                float s = rowdot(g_encT + (size_t)gw*Sn, s_alpha, 64, lane);
                if (!lane) g_ctx[gw] = s * inv;
            }
            if (bid == 0)
                for (int s2 = tid; s2 < Sn; s2 += NT)
                    out[OFF_ALPHA + (size_t)t*Sn + s2] = s_alpha[s2] * inv;
        }
        gsync(ep, bid, nb);

        // ---- Phase D: gi1 ctx-part + GRU1 combine (block-local) + W_pre ctx-part ----
        for (int i = tid; i < Cn; i += NT) s_x[Hn + i] = g_ctx[i];
        __syncthreads();
        for (int it = wid; it < 4*ng; it += 32) {
            int gate = it & 3, il = it >> 2;
            int i = i0 + il;
            if (gate < 3) {
                float s = rowdot(W_ih1 + (size_t)(gate*Hn + i)*2560 + 512, s_x + Hn, 512, lane);
                if (!lane) s_gi[gate*16 + il] = s;
            } else {
                float s = rowdot(W_pre + (size_t)i*3584 + 1536, s_x + Hn, 512, lane);
                if (!lane) g_preacc[i] = s + g_Gpre[(size_t)t*Hn + i];
            }
        }
        __syncthreads();
        if (tid < ng) {
            int i = i0 + tid;
            const float* G = g_G1 + (size_t)t*3*Hn;
            float gir = G[i]        + s_gi[tid]      + b_ih1[i]        + g_gh1[i];
            float giz = G[Hn + i]   + s_gi[16 + tid] + b_ih1[Hn + i]   + g_gh1[Hn + i];
            float gin = G[2*Hn + i] + s_gi[32 + tid] + b_ih1[2*Hn + i];
            float rg = 1.f/(1.f + expf(-gir));
            float zg = 1.f/(1.f + expf(-giz));
            float nn = tanhf(gin + rg * g_gh1[2*Hn + i]);
            float hn = (1.f - zg)*nn + zg*g_h1[i];
            g_h1[i] = hn;
            g_o1[i] = (hn >= 0.f) ? hn : 0.01f*hn;
        }
        gsync(ep, bid, nb);

        // ---- Phase E: gi2 = Wih2 @ [o1; ctx] + GRU2 combine (block-local) ----
        for (int i = tid; i < Hn; i += NT) s_x[i] = g_o1[i];
        __syncthreads();
        for (int it = wid; it < 3*ng; it += 32) {
            int gate = it % 3, il = it / 3;
            int i = i0 + il;
            float s = rowdot(W_ih2 + (size_t)(gate*Hn + i)*3072, s_x, 768, lane);
            if (!lane) s_gi[gate*16 + il] = s;
        }
        __syncthreads();
        if (tid < ng) {
            int i = i0 + tid;
            float gir = s_gi[tid]      + b_ih2[i]        + g_gh2[i];
            float giz = s_gi[16 + tid] + b_ih2[Hn + i]   + g_gh2[Hn + i];
            float gin = s_gi[32 + tid] + b_ih2[2*Hn + i];
            float rg = 1.f/(1.f + expf(-gir));
            float zg = 1.f/(1.f + expf(-giz));
            float nn = tanhf(gin + rg * g_gh2[2*Hn + i]);
            float hn = (1.f - zg)*nn + zg*g_h2[i];
            g_h2[i] = hn;
            g_o2[i] = (hn >= 0.f) ? hn : 0.01f*hn;
        }
        gsync(ep, bid, nb);
    }

    // ======================= EPILOGUE: out[127], pre[127], h1f, h2f =======================
    for (int i = tid; i < Hn; i += NT) s_x[i] = g_o2[i];
    __syncthreads();
    if (gw < 1536) {
        const int r = gw;
        if (r < 512) {
            float s = rowdot(W_out + (size_t)r*Hn, s_x, 256, lane);
            if (!lane) out[(size_t)127*En + r] = s + b_out[r];
        } else {
            int rr = r - 512;
            float s = rowdot(W_pre + (size_t)rr*3584 + 512, s_x, 256, lane);
            if (!lane) {
                float v = s + g_preacc[rr] + b_pre[rr];
                out[OFF_PRE + (size_t)127*Hn + rr] = (v >= 0.f) ? v : 0.01f*v;
            }
        }
    }
    for (int i = bid*NT + tid; i < Hn; i += nb*NT) {
        out[OFF_H1F + i] = g_h1[i];
        out[OFF_H2F + i] = g_h2[i];
    }
}

extern "C" void kernel_launch(void* const* d_in, const int* in_sizes, int n_in,
                              void* d_out, int out_size) {
    (void)in_sizes; (void)n_in; (void)out_size;
    const int*   inputs = (const int*)  d_in[0];
    const float* h1     = (const float*)d_in[1];
    const float* h2     = (const float*)d_in[2];
    const float* pk     = (const float*)d_in[3];
    const float* enc    = (const float*)d_in[4];
    const float* embeds = (const float*)d_in[5];
    const float* Wq     = (const float*)d_in[6];
    const float* v_att  = (const float*)d_in[7];
    const float* W_ih1  = (const float*)d_in[8];
    const float* W_hh1  = (const float*)d_in[9];
    const float* b_ih1  = (const float*)d_in[10];
    const float* b_hh1  = (const float*)d_in[11];
    const float* W_ih2  = (const float*)d_in[12];
    const float* W_hh2  = (const float*)d_in[13];
    const float* b_ih2  = (const float*)d_in[14];
    const float* b_hh2  = (const float*)d_in[15];
    const float* W_pre  = (const float*)d_in[16];
    const float* b_pre  = (const float*)d_in[17];
    const float* W_out  = (const float*)d_in[18];
    const float* b_out  = (const float*)d_in[19];
    float* out = (float*)d_out;

    int dev = 0, nsm = 148;
    cudaGetDevice(&dev);
    cudaDeviceGetAttribute(&nsm, cudaDevAttrMultiProcessorCount, dev);

    init_kernel<<<2, 1024>>>(h1, h2);
    decoder_persistent<<<nsm, NT>>>(inputs, pk, enc, embeds, Wq, v_att,
                                    W_ih1, W_hh1, b_ih1, b_hh1,
                                    W_ih2, W_hh2, b_ih2, b_hh2,
                                    W_pre, b_pre, W_out, b_out, out);
}

// round 9
// speedup vs baseline: 1.6670x; 1.6670x over previous
#include <cuda_runtime.h>
#include <cuda_fp16.h>
#include <math.h>

#define En 512
#define Hn 1024
#define Cn 2048
#define Sn 256
#define Tn 128

#define OFF_PRE   (Tn*En)                 /* 65536  */
#define OFF_ALPHA (OFF_PRE + Tn*Hn)       /* 196608 */
#define OFF_H1F   (OFF_ALPHA + Tn*Sn)     /* 229376 */
#define OFF_H2F   (OFF_H1F + Hn)          /* 230400 */

#define NT 512                             /* threads per block (R2-proven) */

// ---------------- device scratch (static, no allocation) ----------------
__device__ float g_h1[Hn], g_h2[Hn], g_o1[Hn], g_o2[Hn];
__device__ float g_q[Hn], g_e[Sn], g_ctx[Cn];
__device__ float g_gh1[3*Hn], g_gh2[3*Hn];
__device__ float g_preacc[Hn];
__device__ float g_G1[Tn*3*Hn];      // precomputed W_ih1[:, :512] @ emb_t
__device__ float g_Gpre[Tn*Hn];      // precomputed W_pre[:, :512] @ emb_t
__device__ float g_encT[Cn*Sn];      // encoder_outputs transposed (fp32)
__device__ unsigned g_bar;

// fp16 weight copies (converted once per launch in prologue; L2-resident)
__device__ __align__(16) __half hWq   [Hn*Hn];          // 2 MB
__device__ __align__(16) __half hWhh1 [3*Hn*Hn];        // 6 MB
__device__ __align__(16) __half hWhh2 [3*Hn*Hn];        // 6 MB
__device__ __align__(16) __half hWih1c[3*Hn*Cn];        // 12 MB (cols 512..2560)
__device__ __align__(16) __half hWih2 [3*Hn*(Hn+Cn)];   // 18 MB
__device__ __align__(16) __half hWpre [Hn*(Hn+Cn)];     // 6 MB (cols 512..3584)
__device__ __align__(16) __half hWout [En*Hn];          // 1 MB

__global__ void init_kernel(const float* __restrict__ h1, const float* __restrict__ h2) {
    int i = blockIdx.x*blockDim.x + threadIdx.x;
    if (i == 0) g_bar = 0u;
    if (i < Hn) { g_h1[i] = h1[i]; g_h2[i] = h2[i]; }
}

__device__ __forceinline__ float warpsum(float s) {
#pragma unroll
    for (int o = 16; o; o >>= 1) s += __shfl_xor_sync(0xffffffffu, s, o);
    return s;
}

__device__ __forceinline__ float2 h2f(unsigned u) {
    __half2 h;
    *reinterpret_cast<unsigned*>(&h) = u;
    return __half22float2(h);
}

// warp-cooperative fp32 row dot (global row x shared vec)
__device__ __forceinline__ float rowdot(const float* __restrict__ Wrow,
                                        const float* __restrict__ xs,
                                        int n4, int lane) {
    const float4* __restrict__ W4 = (const float4*)Wrow;
    const float4* __restrict__ X4 = (const float4*)xs;
    float s = 0.f;
#pragma unroll 8
    for (int k = lane; k < n4; k += 32) {
        float4 w = __ldg(W4 + k);
        float4 x = X4[k];
        s += w.x*x.x + w.y*x.y + w.z*x.z + w.w*x.w;
    }
    return warpsum(s);
}

// warp-cooperative fp16 row dot (row width = NI*256 elements), fp32 accumulate
template<int NI>
__device__ __forceinline__ float dotb(const __half* __restrict__ row,
                                      const float* __restrict__ xs, int lane) {
    const uint4*  W = (const uint4*)row;
    const float4* X = (const float4*)xs;
    float s = 0.f;
#pragma unroll
    for (int k = 0; k < NI; k++) {
        uint4 w = __ldg(W + k*32 + lane);
        int xi = (k*32 + lane)*2;
        float4 a0 = X[xi], a1 = X[xi+1];
        float2 f;
        f = h2f(w.x); s += f.x*a0.x + f.y*a0.y;
        f = h2f(w.y); s += f.x*a0.z + f.y*a0.w;
        f = h2f(w.z); s += f.x*a1.x + f.y*a1.y;
        f = h2f(w.w); s += f.x*a1.z + f.y*a1.w;
    }
    return warpsum(s);
}

// grid barrier (R2-proven): atomic counter + gpu-scope fences
__device__ __forceinline__ void gsync(unsigned &ep) {
    ep++;
    __syncthreads();
    if (threadIdx.x == 0) {
        __threadfence();                  // release (CCTL.IVALL)
        atomicAdd(&g_bar, 1u);
        unsigned target = ep * gridDim.x;
        volatile unsigned* p = &g_bar;
        while (*p < target) { }
        __threadfence();                  // acquire
    }
    __syncthreads();
}

extern "C" __global__ void __launch_bounds__(NT, 1)
decoder_persistent(
    const int*   __restrict__ inputs,
    const float* __restrict__ pk,
    const float* __restrict__ enc,
    const float* __restrict__ embeds,
    const float* __restrict__ Wq,
    const float* __restrict__ v_att,
    const float* __restrict__ W_ih1,
    const float* __restrict__ W_hh1,
    const float* __restrict__ b_ih1,
    const float* __restrict__ b_hh1,
    const float* __restrict__ W_ih2,
    const float* __restrict__ W_hh2,
    const float* __restrict__ b_ih2,
    const float* __restrict__ b_hh2,
    const float* __restrict__ W_pre,
    const float* __restrict__ b_pre,
    const float* __restrict__ W_out,
    const float* __restrict__ b_out,
    float* __restrict__ out)
{
    __shared__ __align__(16) float s_x[8192];     // 32 KB staging
    __shared__ __align__(16) float s_alpha[Sn];
    __shared__ float s_gi[48];
    __shared__ float s_inv;

    const int tid  = threadIdx.x;
    const int lane = tid & 31;
    const int wid  = tid >> 5;                    // 0..15
    const int nb   = gridDim.x;
    const int bid  = blockIdx.x;
    const int nwg  = nb * 16;                     // total warps in grid
    const int gw   = bid*16 + wid;                // global warp id
    const int gth  = bid*NT + tid;
    const int gstr = nb*NT;
    unsigned ep = 0;

    // ======================= PROLOGUE =======================
    // 1) transpose encoder_outputs -> encT[c][s] (fp32)
    for (int idx = gth; idx < Cn*Sn; idx += gstr) {
        int c = idx >> 8, s = idx & 255;
        g_encT[idx] = enc[(size_t)s*Cn + c];
    }
    // 2) fp32 -> fp16 weight conversion
    for (int i = gth; i < Hn*Hn/2; i += gstr)
        ((__half2*)hWq)[i] = __float22half2_rn(((const float2*)Wq)[i]);
    for (int i = gth; i < 3*Hn*Hn/2; i += gstr)
        ((__half2*)hWhh1)[i] = __float22half2_rn(((const float2*)W_hh1)[i]);
    for (int i = gth; i < 3*Hn*Hn/2; i += gstr)
        ((__half2*)hWhh2)[i] = __float22half2_rn(((const float2*)W_hh2)[i]);
    for (int i = gth; i < 3*Hn*(Hn+Cn)/2; i += gstr)
        ((__half2*)hWih2)[i] = __float22half2_rn(((const float2*)W_ih2)[i]);
    for (int i = gth; i < En*Hn/2; i += gstr)
        ((__half2*)hWout)[i] = __float22half2_rn(((const float2*)W_out)[i]);
    for (int i = gth; i < 3*Hn*(Cn/2); i += gstr) {        // W_ih1 cols 512..2560
        int r = i >> 10, c = i & 1023;
        float2 f = *(const float2*)(W_ih1 + (size_t)r*2560 + 512 + 2*c);
        ((__half2*)hWih1c)[i] = __float22half2_rn(f);
    }
    for (int i = gth; i < Hn*((Hn+Cn)/2); i += gstr) {     // W_pre cols 512..3584
        int r = i / 1536, c = i % 1536;
        float2 f = *(const float2*)(W_pre + (size_t)r*3584 + 512 + 2*c);
        ((__half2*)hWpre)[i] = __float22half2_rn(f);
    }
    // 3) emb-part GEMMs (fp32, per-launch): g_G1, g_Gpre
    {
        const int RT = 4*Hn;                       // 4096 rows
        int rb = (RT + nb - 1)/nb;
        int r0 = bid*rb, r1 = min(RT, r0 + rb);
        for (int tile = 0; tile < Tn/16; tile++) {
            __syncthreads();
            for (int idx = tid; idx < 16*En; idx += NT) {
                int tt = idx >> 9, c = idx & 511;
                s_x[idx] = embeds[(size_t)inputs[tile*16 + tt]*En + c];
            }
            __syncthreads();
            for (int rI = r0 + wid; rI < r1; rI += 16) {
                const float* Wrow; float* Gp; int gs;
                if (rI < 3*Hn) { Wrow = W_ih1 + (size_t)rI*2560;          Gp = g_G1  + rI;          gs = 3*Hn; }
                else           { Wrow = W_pre + (size_t)(rI - 3*Hn)*3584; Gp = g_Gpre + (rI - 3*Hn); gs = Hn;  }
                float w[16];
#pragma unroll
                for (int k = 0; k < 16; k++) w[k] = __ldg(Wrow + k*32 + lane);
#pragma unroll
                for (int tt = 0; tt < 16; tt++) {
                    float s = 0.f;
#pragma unroll
                    for (int k = 0; k < 16; k++) s += w[k] * s_x[tt*512 + k*32 + lane];
                    s = warpsum(s);
                    if (lane == 0) Gp[(tile*16 + tt)*gs] = s;
                }
            }
        }
    }
    gsync(ep);

    const int GPB = (Hn + nb - 1)/nb;               // GRU rows owned per block
    const int i0  = bid*GPB;
    const int ng  = max(0, min(GPB, Hn - i0));

    // ======================= MAIN SEQUENTIAL LOOP =======================
    for (int t = 0; t < Tn; t++) {
        // ---- Phase A: q=Wq@h2, gh1=Whh1@h1+b, gh2=Whh2@h2+b, (t>0) out[t-1], pre[t-1] ----
        for (int i = tid; i < Hn; i += NT) {
            s_x[i]        = g_h2[i];
            s_x[Hn + i]   = g_h1[i];
            s_x[2*Hn + i] = g_o2[i];
        }
        __syncthreads();
        {
            int tot = (t > 0) ? 8704 : 7168;
            for (int r = gw; r < tot; r += nwg) {
                if (r < 1024) {
                    float s = dotb<4>(hWq + (size_t)r*Hn, s_x, lane);
                    if (!lane) g_q[r] = s;
                } else if (r < 4096) {
                    int rr = r - 1024;
                    float s = dotb<4>(hWhh1 + (size_t)rr*Hn, s_x + Hn, lane);
                    if (!lane) g_gh1[rr] = s + b_hh1[rr];
                } else if (r < 7168) {
                    int rr = r - 4096;
                    float s = dotb<4>(hWhh2 + (size_t)rr*Hn, s_x, lane);
                    if (!lane) g_gh2[rr] = s + b_hh2[rr];
                } else if (r < 7680) {
                    int rr = r - 7168;
                    float s = dotb<4>(hWout + (size_t)rr*Hn, s_x + 2*Hn, lane);
                    if (!lane) out[(size_t)(t-1)*En + rr] = s + b_out[rr];
                } else {
                    int rr = r - 7680;
                    float s = dotb<4>(hWpre + (size_t)rr*(Hn+Cn), s_x + 2*Hn, lane);
                    if (!lane) {
                        float v = s + g_preacc[rr] + b_pre[rr];
                        out[OFF_PRE + (size_t)(t-1)*Hn + rr] = (v >= 0.f) ? v : 0.01f*v;
                    }
                }
            }
        }
        gsync(ep);

        // ---- Phase B: attention energies e[s] = tanh(pk[s]+q) . v_att ----
        for (int i = tid; i < Hn; i += NT) s_x[i] = g_q[i];
        __syncthreads();
        for (int r = gw; r < Sn; r += nwg) {
            const float4* p4 = (const float4*)(pk + (size_t)r*Hn);
            const float4* x4 = (const float4*)s_x;
            const float4* v4 = (const float4*)v_att;
            float acc = 0.f;
#pragma unroll 4
            for (int k = lane; k < 256; k += 32) {
                float4 p = __ldg(p4 + k); float4 q = x4[k]; float4 v = __ldg(v4 + k);
                acc += tanhf(p.x + q.x)*v.x + tanhf(p.y + q.y)*v.y
                     + tanhf(p.z + q.z)*v.z + tanhf(p.w + q.w)*v.w;
            }
            acc = warpsum(acc);
            if (!lane) g_e[r] = acc;
        }
        gsync(ep);

        // ---- Phase C: per-block softmax (redundant, cheap) + context = alpha @ enc ----
        if (wid == 0) {
            float ev[8], m = -1e30f;
#pragma unroll
            for (int k = 0; k < 8; k++) { ev[k] = g_e[k*32 + lane]; m = fmaxf(m, ev[k]); }
#pragma unroll
            for (int o = 16; o; o >>= 1) m = fmaxf(m, __shfl_xor_sync(0xffffffffu, m, o));
            float sum = 0.f;
#pragma unroll
            for (int k = 0; k < 8; k++) { float a = expf(ev[k] - m); s_alpha[k*32 + lane] = a; sum += a; }
            sum = warpsum(sum);
            if (!lane) s_inv = 1.f/sum;
        }
        __syncthreads();
        {
            float inv = s_inv;
            for (int c = gw; c < Cn; c += nwg) {
                float s = rowdot(g_encT + (size_t)c*Sn, s_alpha, 64, lane);
                if (!lane) g_ctx[c] = s * inv;
            }
            if (bid == 0)
                for (int s2 = tid; s2 < Sn; s2 += NT)
                    out[OFF_ALPHA + (size_t)t*Sn + s2] = s_alpha[s2] * inv;
        }
        gsync(ep);

        // ---- Phase D: gi1 ctx-part + W_pre ctx-part + GRU1 combine (block-local) ----
        for (int i = tid; i < Cn; i += NT) s_x[Hn + i] = g_ctx[i];
        __syncthreads();
        for (int it = wid; it < 4*ng; it += 16) {
            int gate = it & 3, il = it >> 2;
            int i = i0 + il;
            if (gate < 3) {
                float s = dotb<8>(hWih1c + (size_t)(gate*Hn + i)*Cn, s_x + Hn, lane);
                if (!lane) s_gi[gate*16 + il] = s;
            } else {
                float s = dotb<8>(hWpre + (size_t)i*(Hn+Cn) + Hn, s_x + Hn, lane);
                if (!lane) g_preacc[i] = s + g_Gpre[(size_t)t*Hn + i];
            }
        }
        __syncthreads();
        if (tid < ng) {
            int i = i0 + tid;
            const float* G = g_G1 + (size_t)t*3*Hn;
            float gir = G[i]        + s_gi[tid]      + b_ih1[i]        + g_gh1[i];
            float giz = G[Hn + i]   + s_gi[16 + tid] + b_ih1[Hn + i]   + g_gh1[Hn + i];
            float gin = G[2*Hn + i] + s_gi[32 + tid] + b_ih1[2*Hn + i];
            float rg = 1.f/(1.f + expf(-gir));
            float zg = 1.f/(1.f + expf(-giz));
            float nn = tanhf(gin + rg * g_gh1[2*Hn + i]);
            float hn = (1.f - zg)*nn + zg*g_h1[i];
            g_h1[i] = hn;
            g_o1[i] = (hn >= 0.f) ? hn : 0.01f*hn;
        }
        gsync(ep);

        // ---- Phase E: gi2 = Wih2 @ [o1; ctx] + GRU2 combine (block-local) ----
        for (int i = tid; i < Hn; i += NT) s_x[i] = g_o1[i];   // ctx persists at s_x[1024..3072)
        __syncthreads();
        for (int it = wid; it < 3*ng; it += 16) {
            int gate = it % 3, il = it / 3;
            int i = i0 + il;
            float s = dotb<12>(hWih2 + (size_t)(gate*Hn + i)*(Hn+Cn), s_x, lane);
            if (!lane) s_gi[gate*16 + il] = s;
        }
        __syncthreads();
        if (tid < ng) {
            int i = i0 + tid;
            float gir = s_gi[tid]      + b_ih2[i]        + g_gh2[i];
            float giz = s_gi[16 + tid] + b_ih2[Hn + i]   + g_gh2[Hn + i];
            float gin = s_gi[32 + tid] + b_ih2[2*Hn + i];
            float rg = 1.f/(1.f + expf(-gir));
            float zg = 1.f/(1.f + expf(-giz));
            float nn = tanhf(gin + rg * g_gh2[2*Hn + i]);
            float hn = (1.f - zg)*nn + zg*g_h2[i];
            g_h2[i] = hn;
            g_o2[i] = (hn >= 0.f) ? hn : 0.01f*hn;
        }
        gsync(ep);
    }

    // ======================= EPILOGUE: out[127], pre[127], h1f, h2f =======================
    for (int i = tid; i < Hn; i += NT) s_x[i] = g_o2[i];
    __syncthreads();
    for (int r = gw; r < 1536; r += nwg) {
        if (r < 512) {
            float s = dotb<4>(hWout + (size_t)r*Hn, s_x, lane);
            if (!lane) out[(size_t)127*En + r] = s + b_out[r];
        } else {
            int rr = r - 512;
            float s = dotb<4>(hWpre + (size_t)rr*(Hn+Cn), s_x, lane);
            if (!lane) {
                float v = s + g_preacc[rr] + b_pre[rr];
                out[OFF_PRE + (size_t)127*Hn + rr] = (v >= 0.f) ? v : 0.01f*v;
            }
        }
    }
    for (int i = gth; i < Hn; i += gstr) {
        out[OFF_H1F + i] = g_h1[i];
        out[OFF_H2F + i] = g_h2[i];
    }
}

extern "C" void kernel_launch(void* const* d_in, const int* in_sizes, int n_in,
                              void* d_out, int out_size) {
    (void)in_sizes; (void)n_in; (void)out_size;
    const int*   inputs = (const int*)  d_in[0];
    const float* h1     = (const float*)d_in[1];
    const float* h2     = (const float*)d_in[2];
    const float* pk     = (const float*)d_in[3];
    const float* enc    = (const float*)d_in[4];
    const float* embeds = (const float*)d_in[5];
    const float* Wq     = (const float*)d_in[6];
    const float* v_att  = (const float*)d_in[7];
    const float* W_ih1  = (const float*)d_in[8];
    const float* W_hh1  = (const float*)d_in[9];
    const float* b_ih1  = (const float*)d_in[10];
    const float* b_hh1  = (const float*)d_in[11];
    const float* W_ih2  = (const float*)d_in[12];
    const float* W_hh2  = (const float*)d_in[13];
    const float* b_ih2  = (const float*)d_in[14];
    const float* b_hh2  = (const float*)d_in[15];
    const float* W_pre  = (const float*)d_in[16];
    const float* b_pre  = (const float*)d_in[17];
    const float* W_out  = (const float*)d_in[18];
    const float* b_out  = (const float*)d_in[19];
    float* out = (float*)d_out;

    int dev = 0, nsm = 148;
    cudaGetDevice(&dev);
    cudaDeviceGetAttribute(&nsm, cudaDevAttrMultiProcessorCount, dev);

    init_kernel<<<2, 1024>>>(h1, h2);
    decoder_persistent<<<nsm, NT>>>(inputs, pk, enc, embeds, Wq, v_att,
                                    W_ih1, W_hh1, b_ih1, b_hh1,
                                    W_ih2, W_hh2, b_ih2, b_hh2,
                                    W_pre, b_pre, W_out, b_out, out);
}